// round 16
// baseline (speedup 1.0000x reference)
#include <cuda_runtime.h>
#include <cstdint>
#include <math.h>

// Problem constants
#define Bc     2
#define Nn     512
#define NODES  (Bc * Nn)
#define Kn     30
#define HIDc   128
#define HEADSc 4
#define Dhd    32
#define FFc    512
#define Lc     3
#define OUTc   400
#define ROWS   32    // Kn padded to 32
#define HIDP   132   // padded row stride (floats)
#define KT     16    // k-steps per staged weight tile

typedef unsigned long long u64;
typedef unsigned int       u32;

// Device scratch (allocation-free rule: __device__ globals)
__device__ float g_hV  [NODES * HIDc];
__device__ float g_PK0 [Lc * NODES * HIDc];   // h_V @ WK[l, 0:128]
__device__ float g_PK1 [Lc * NODES * HIDc];   // h_V @ WK[l, 128:256]
__device__ float g_PV0 [Lc * NODES * HIDc];   // h_V @ WV[l, 0:128]
__device__ float g_PV1 [Lc * NODES * HIDc];   // h_V @ WV[l, 128:256]
__device__ float g_hout[(size_t)NODES * Kn * OUTc];

struct Smem {
    float sW [2 * KT][HIDc]; // staged weight tiles (double buffer, 16 KB)
    float sE [ROWS][HIDP];   // current h_E
    float sA [ROWS][HIDP];   // scratch: E-in / Q / upd / FF t-chunk
    float sK [ROWS][HIDP];
    float sV [ROWS][HIDP];
    float sP [HEADSc][ROWS][ROWS];  // attention probs
    float sMa[ROWS];         // mask_attend row
    int   sIdx[ROWS];        // E_idx row
};

// ---- packed fp32x2 primitives (FFMA2 path, sm_103a) ----
__device__ __forceinline__ u64 pack2(float x, float y) {
    u64 r; asm("mov.b64 %0, {%1, %2};" : "=l"(r) : "f"(x), "f"(y)); return r;
}
__device__ __forceinline__ void unpack2(u64 v, float& x, float& y) {
    asm("mov.b64 {%0, %1}, %2;" : "=f"(x), "=f"(y) : "l"(v));
}
__device__ __forceinline__ void fma2(u64& d, u64 a, u64 b) {
    asm("fma.rn.f32x2 %0, %1, %2, %0;" : "+l"(d) : "l"(a), "l"(b));
}

// ---- cp.async helpers ----
__device__ __forceinline__ void cp_async16(u32 dst, const void* src) {
    asm volatile("cp.async.cg.shared.global [%0], [%1], 16;\n" :: "r"(dst), "l"(src));
}
__device__ __forceinline__ void cp_commit() {
    asm volatile("cp.async.commit_group;\n" ::: "memory");
}
__device__ __forceinline__ void cp_wait0() {
    asm volatile("cp.async.wait_group 0;\n" ::: "memory");
}

// Stage KT k-rows x 128 cols of W into sW[buf]. 128 threads: thread = (k, 64B seg).
__device__ __forceinline__ void stage_tile(
    float (*sW)[HIDc], const float* __restrict__ W, int ldw, int kt0, int tid)
{
    int k   = tid >> 3;          // 0..15
    int seg = (tid & 7) * 16;    // float offset 0,16,...,112
    const float* src = W + (size_t)(kt0 + k) * ldw + seg;
    u32 dst = (u32)__cvta_generic_to_shared(&sW[k][seg]);
#pragma unroll
    for (int i = 0; i < 4; ++i)
        cp_async16(dst + i * 16, src + i * 4);
    cp_commit();
}

// Compute one KT-step tile from staged weights.
__device__ __forceinline__ void compute_tile(
    const float (* __restrict__ buf)[HIDc], const float (* __restrict__ A)[HIDP],
    int kb, u64 acc[4][4], int rowb, int col0)
{
#pragma unroll
    for (int k = 0; k < KT; ++k) {
        ulonglong2 w0 = *reinterpret_cast<const ulonglong2*>(&buf[k][col0]);
        ulonglong2 w1 = *reinterpret_cast<const ulonglong2*>(&buf[k][col0 + 4]);
#pragma unroll
        for (int r = 0; r < 4; ++r) {
            float av = A[rowb + r][kb + k];
            u64 s = pack2(av, av);
            fma2(acc[r][0], s, w0.x);
            fma2(acc[r][1], s, w0.y);
            fma2(acc[r][2], s, w1.x);
            fma2(acc[r][3], s, w1.y);
        }
    }
}

// SMEM-staged GEMM: acc[r][j] += sum_k A[rowb+r][k] * W[k*ldw + col0 + 2j..]
// kd=128. Weight tiles staged CTA-wide via cp.async (8x less L2 traffic).
// MUST be called by all 128 threads (contains __syncthreads).
__device__ __forceinline__ void gemm_staged(
    const float (* __restrict__ A)[HIDP], const float* __restrict__ W, int ldw,
    u64 acc[4][4], int rowb, int col0, float (*sW)[HIDc], int tid)
{
    stage_tile(sW, W, ldw, 0, tid);
#pragma unroll 1
    for (int t = 0; t < HIDc / KT; ++t) {
        cp_wait0();
        __syncthreads();                 // tile t visible CTA-wide; buf[(t+1)&1] free
        if (t + 1 < HIDc / KT)
            stage_tile(sW + ((t + 1) & 1) * KT, W, ldw, (t + 1) * KT, tid);
        compute_tile(sW + (t & 1) * KT, A, t * KT, acc, rowb, col0);
    }
    __syncthreads();                     // all reads of sW/A done before caller reuses
}

// Clamped single-buffer staged GEMM (for Wout partial chunk; scalar staging).
__device__ __forceinline__ void gemm_staged_clamped(
    const float (* __restrict__ A)[HIDP], const float* __restrict__ W, int ldw,
    int maxc, u64 acc[4][4], int rowb, int col0, float (*sW)[HIDc], int tid)
{
    int k   = tid >> 3;
    int seg = (tid & 7) * 16;
#pragma unroll 1
    for (int t = 0; t < HIDc / KT; ++t) {
#pragma unroll
        for (int i = 0; i < 16; ++i) {
            int c = seg + i;
            sW[k][c] = (c < maxc) ? W[(size_t)(t * KT + k) * ldw + c] : 0.0f;
        }
        __syncthreads();
        compute_tile(sW, A, t * KT, acc, rowb, col0);
        __syncthreads();
    }
}

__device__ __forceinline__ void unpack_acc(const u64 a[4], float o[8]) {
    unpack2(a[0], o[0], o[1]); unpack2(a[1], o[2], o[3]);
    unpack2(a[2], o[4], o[5]); unpack2(a[3], o[6], o[7]);
}

__device__ __forceinline__ void store8(float* dst, const float o[8]) {
    *reinterpret_cast<float4*>(dst)     = make_float4(o[0], o[1], o[2], o[3]);
    *reinterpret_cast<float4*>(dst + 4) = make_float4(o[4], o[5], o[6], o[7]);
}

// Register-pipelined LDG GEMM (kept for the small proj kernel).
__device__ __forceinline__ void gemm_acc2(
    const float (* __restrict__ A)[HIDP], const float* __restrict__ W, int ldw,
    u64 acc[4][4], int rowb, int col0)
{
    const float* wp = W + col0;
    ulonglong2 a0[4], a1[4], b0[4], b1[4];
#pragma unroll
    for (int k = 0; k < 4; ++k) {
        const float* p = wp + (size_t)k * ldw;
        a0[k] = *reinterpret_cast<const ulonglong2*>(p);
        a1[k] = *reinterpret_cast<const ulonglong2*>(p + 4);
    }
#pragma unroll 1
    for (int kb = 0; kb < HIDc; kb += 8) {
#pragma unroll
        for (int k = 0; k < 4; ++k) {
            const float* p = wp + (size_t)(kb + 4 + k) * ldw;
            b0[k] = *reinterpret_cast<const ulonglong2*>(p);
            b1[k] = *reinterpret_cast<const ulonglong2*>(p + 4);
        }
#pragma unroll
        for (int k = 0; k < 4; ++k)
#pragma unroll
            for (int r = 0; r < 4; ++r) {
                float av = A[rowb + r][kb + k];
                u64 s = pack2(av, av);
                fma2(acc[r][0], s, a0[k].x); fma2(acc[r][1], s, a0[k].y);
                fma2(acc[r][2], s, a1[k].x); fma2(acc[r][3], s, a1[k].y);
            }
        if (kb + 8 < HIDc) {
#pragma unroll
            for (int k = 0; k < 4; ++k) {
                const float* p = wp + (size_t)(kb + 8 + k) * ldw;
                a0[k] = *reinterpret_cast<const ulonglong2*>(p);
                a1[k] = *reinterpret_cast<const ulonglong2*>(p + 4);
            }
        }
#pragma unroll
        for (int k = 0; k < 4; ++k)
#pragma unroll
            for (int r = 0; r < 4; ++r) {
                float av = A[rowb + r][kb + 4 + k];
                u64 s = pack2(av, av);
                fma2(acc[r][0], s, b0[k].x); fma2(acc[r][1], s, b0[k].y);
                fma2(acc[r][2], s, b1[k].x); fma2(acc[r][3], s, b1[k].y);
            }
    }
}

// Reference norm: mu=mean, sigma=sqrt(var_ddof1+1e-6),
// out = (g*(x-mu)/(sigma+1e-6)+b)*scale
__device__ __forceinline__ void layer_norm(
    float (*X)[HIDP], const float* __restrict__ g, const float* __restrict__ bta,
    float scale, int tid)
{
    int lane = tid & 31, wid = tid >> 5;
    for (int row = wid; row < Kn; row += 4) {
        float v0 = X[row][lane], v1 = X[row][lane + 32];
        float v2 = X[row][lane + 64], v3 = X[row][lane + 96];
        float s = v0 + v1 + v2 + v3;
#pragma unroll
        for (int o = 16; o; o >>= 1) s += __shfl_xor_sync(0xffffffffu, s, o);
        float mu = s * (1.0f / HIDc);
        float d0 = v0 - mu, d1 = v1 - mu, d2 = v2 - mu, d3 = v3 - mu;
        float vs = d0 * d0 + d1 * d1 + d2 * d2 + d3 * d3;
#pragma unroll
        for (int o = 16; o; o >>= 1) vs += __shfl_xor_sync(0xffffffffu, vs, o);
        float sigma = sqrtf(vs * (1.0f / (HIDc - 1)) + 1e-6f);
        float invs = 1.0f / (sigma + 1e-6f);
        X[row][lane]      = (g[lane]      * d0 * invs + bta[lane])      * scale;
        X[row][lane + 32] = (g[lane + 32] * d1 * invs + bta[lane + 32]) * scale;
        X[row][lane + 64] = (g[lane + 64] * d2 * invs + bta[lane + 64]) * scale;
        X[row][lane + 96] = (g[lane + 96] * d3 * invs + bta[lane + 96]) * scale;
    }
}

// ---------------------------------------------------------------------------
// Kernel 1: h_V = V @ Wv_w + Wv_b
// ---------------------------------------------------------------------------
__global__ void hv_kernel(const float* __restrict__ V,
                          const float* __restrict__ Wv_w,
                          const float* __restrict__ Wv_b)
{
    __shared__ float sv[HIDc];
    int bn = blockIdx.x;
    int tid = threadIdx.x;
    sv[tid] = V[(size_t)bn * HIDc + tid];
    __syncthreads();
    float acc = Wv_b[tid];
#pragma unroll 8
    for (int k = 0; k < HIDc; ++k)
        acc = fmaf(sv[k], Wv_w[k * HIDc + tid], acc);
    g_hV[(size_t)bn * HIDc + tid] = acc;
}

// ---------------------------------------------------------------------------
// Kernel 1b: per-node projections. blockIdx.x = node tile (32 nodes),
// blockIdx.y = l*4 + t,  t in {PK0, PK1, PV0, PV1}.
// ---------------------------------------------------------------------------
__global__ void __launch_bounds__(128)
proj_kernel(const float* __restrict__ WK, const float* __restrict__ WV)
{
    __shared__ float sHV[ROWS][HIDP];
    const int tid  = threadIdx.x;
    const int node0 = blockIdx.x * ROWS;
    const int j    = blockIdx.y;
    const int l    = j >> 2;
    const int t    = j & 3;
    const int rowb = (tid >> 4) * 4;
    const int col0 = (tid & 15) * 8;

    for (int i = tid; i < ROWS * HIDc; i += 128) {
        int r = i >> 7, c = i & 127;
        sHV[r][c] = g_hV[(size_t)(node0 + r) * HIDc + c];
    }
    __syncthreads();

    const float* W = ((t < 2) ? WK : WV) + (size_t)l * 3 * HIDc * HIDc
                     + (size_t)(t & 1) * HIDc * HIDc;
    float* out = (t == 0 ? g_PK0 : t == 1 ? g_PK1 : t == 2 ? g_PV0 : g_PV1)
                 + (size_t)l * NODES * HIDc;

    u64 acc[4][4] = {};
    gemm_acc2(sHV, W, HIDc, acc, rowb, col0);
#pragma unroll
    for (int r = 0; r < 4; ++r) {
        float o[8]; unpack_acc(acc[r], o);
        store8(&out[(size_t)(node0 + rowb + r) * HIDc + col0], o);
    }
}

// ---------------------------------------------------------------------------
// Kernel 2: fused h_E init + 3 transformer layers + output projection.
// One block per (b,n). 128 threads, 2 blocks/SM. Weights staged in SMEM.
// ---------------------------------------------------------------------------
extern "C" __global__ void __launch_bounds__(128, 2)
pair_layers_kernel(
    const float* __restrict__ E, const float* __restrict__ xmask,
    const int* __restrict__ Eidx,
    const float* __restrict__ We_w, const float* __restrict__ We_b,
    const float* __restrict__ WQ, const float* __restrict__ WK,
    const float* __restrict__ WV, const float* __restrict__ WO,
    const float* __restrict__ ln1g, const float* __restrict__ ln1b,
    const float* __restrict__ ln2g, const float* __restrict__ ln2b,
    const float* __restrict__ f1w, const float* __restrict__ f1b,
    const float* __restrict__ f2w, const float* __restrict__ f2b,
    const float* __restrict__ Wout_w, const float* __restrict__ Wout_b)
{
    extern __shared__ char smraw[];
    Smem& sm = *reinterpret_cast<Smem*>(smraw);

    const int bn   = blockIdx.x;
    const int b    = bn / Nn;
    const int tid  = threadIdx.x;
    const int rowb = (tid >> 4) * 4;        // 4 rows per thread
    const int col0 = (tid & 15) * 8;        // 8 cols per thread

    // --- Stage inputs ---
    const int* eRow = Eidx + (size_t)bn * Kn;
    const float* Eblk = E + (size_t)bn * Kn * HIDc;
    for (int i = tid; i < ROWS * HIDc; i += 128) {
        int r = i >> 7, c = i & 127;
        sm.sA[r][c] = (r < Kn) ? Eblk[r * HIDc + c] : 0.0f;
    }
    if (tid < ROWS) {
        int j = (tid < Kn) ? eRow[tid] : 0;
        sm.sIdx[tid] = j;
        sm.sMa[tid] = (tid < Kn) ? xmask[b * Nn + j] * xmask[bn] : 0.0f;
    }
    __syncthreads();

    // --- h_E = E @ We_w + We_b ---
    {
        u64 acc[4][4] = {};
        gemm_staged(sm.sA, We_w, HIDc, acc, rowb, col0, sm.sW, tid);
#pragma unroll
        for (int r = 0; r < 4; ++r) {
            int row = rowb + r;
            float o[8]; unpack_acc(acc[r], o);
#pragma unroll
            for (int c = 0; c < 8; ++c)
                o[c] = (row < Kn) ? o[c] + We_b[col0 + c] : 0.0f;
            store8(&sm.sE[row][col0], o);
        }
    }
    // sE stores become visible via the first internal barrier of the next gemm.

    const float att_scale = 0.17677669529663689f;  // 1/sqrt(32)

#pragma unroll 1
    for (int l = 0; l < Lc; ++l) {
        const float* wq  = WQ + (size_t)l * HIDc * HIDc;
        const float* wk2 = WK + (size_t)l * 3 * HIDc * HIDc + 2 * HIDc * HIDc;
        const float* wv2 = WV + (size_t)l * 3 * HIDc * HIDc + 2 * HIDc * HIDc;
        const float* wo  = WO + (size_t)l * HIDc * HIDc;

        // Gather per-node precomputed K/V contributions into sK/sV.
        {
            int self = sm.sIdx[0];
            const float* pk0 = g_PK0 + ((size_t)l * NODES + b * Nn + self) * HIDc;
            const float* pv0 = g_PV0 + ((size_t)l * NODES + b * Nn + self) * HIDc;
            float k0 = pk0[tid], v0 = pv0[tid];
#pragma unroll 2
            for (int r = 0; r < Kn; ++r) {
                size_t nidx = (size_t)l * NODES + b * Nn + sm.sIdx[r];
                sm.sK[r][tid] = k0 + g_PK1[nidx * HIDc + tid];
                sm.sV[r][tid] = v0 + g_PV1[nidx * HIDc + tid];
            }
            sm.sK[30][tid] = 0.0f; sm.sK[31][tid] = 0.0f;
            sm.sV[30][tid] = 0.0f; sm.sV[31][tid] = 0.0f;
        }

        // Q = h_E @ WQ  (internal barriers make sE + gathered sK/sV visible)
        {
            u64 qacc[4][4] = {};
            gemm_staged(sm.sE, wq, HIDc, qacc, rowb, col0, sm.sW, tid);
#pragma unroll
            for (int r = 0; r < 4; ++r) {
                float o[8]; unpack_acc(qacc[r], o);
                store8(&sm.sA[rowb + r][col0], o);
            }
        }

        // K += h_E @ WK2 ; V += h_E @ WV2  (seed from gathered tiles; regions
        // read/written per-thread disjoint)
        {
            u64 acc[4][4];
#pragma unroll
            for (int r = 0; r < 4; ++r)
#pragma unroll
                for (int jj = 0; jj < 4; ++jj)
                    acc[r][jj] = *reinterpret_cast<const u64*>(&sm.sK[rowb + r][col0 + 2 * jj]);
            gemm_staged(sm.sE, wk2, HIDc, acc, rowb, col0, sm.sW, tid);
#pragma unroll
            for (int r = 0; r < 4; ++r) {
                float o[8]; unpack_acc(acc[r], o);
                store8(&sm.sK[rowb + r][col0], o);
            }
        }
        {
            u64 acc[4][4];
#pragma unroll
            for (int r = 0; r < 4; ++r)
#pragma unroll
                for (int jj = 0; jj < 4; ++jj)
                    acc[r][jj] = *reinterpret_cast<const u64*>(&sm.sV[rowb + r][col0 + 2 * jj]);
            gemm_staged(sm.sE, wv2, HIDc, acc, rowb, col0, sm.sW, tid);
#pragma unroll
            for (int r = 0; r < 4; ++r) {
                float o[8]; unpack_acc(acc[r], o);
                store8(&sm.sV[rowb + r][col0], o);
            }
        }
        __syncthreads();   // Q (sA), K, V stores visible CTA-wide for logits

        // logits (masked) -> sP
        for (int idx = tid; idx < HEADSc * Kn * Kn; idx += 128) {
            int h   = idx / (Kn * Kn);
            int rem = idx % (Kn * Kn);
            int q   = rem / Kn;
            int kk  = rem % Kn;
            const u64* qp = reinterpret_cast<const u64*>(&sm.sA[q][h * Dhd]);
            const u64* kp = reinterpret_cast<const u64*>(&sm.sK[kk][h * Dhd]);
            u64 acc = 0ULL;
#pragma unroll
            for (int d = 0; d < Dhd / 2; ++d) fma2(acc, qp[d], kp[d]);
            float lo, hi; unpack2(acc, lo, hi);
            float dot = lo + hi;
            float m = sm.sMa[q] * sm.sMa[kk];
            sm.sP[h][q][kk] = (m > 0.0f) ? dot * att_scale : -3.402823466e38f;
        }
        __syncthreads();

        // softmax over kk, then * mask
        if (tid < HEADSc * Kn) {
            int h = tid / Kn, q = tid % Kn;
            float mx = -3.402823466e38f;
            for (int kk = 0; kk < Kn; ++kk) mx = fmaxf(mx, sm.sP[h][q][kk]);
            float s = 0.0f;
            for (int kk = 0; kk < Kn; ++kk) {
                float e = __expf(sm.sP[h][q][kk] - mx);
                sm.sP[h][q][kk] = e;
                s += e;
            }
            float inv = 1.0f / s;
            float mq = sm.sMa[q];
            for (int kk = 0; kk < Kn; ++kk)
                sm.sP[h][q][kk] = sm.sP[h][q][kk] * inv * (mq * sm.sMa[kk]);
        }
        __syncthreads();

        // upd = P @ V (per head) -> sA (Q dead; logits barrier passed)
        {
            u64 acc[4][4] = {};
            int h = col0 >> 5;
            for (int kk = 0; kk < Kn; ++kk) {
                const float* vr = &sm.sV[kk][col0];
                ulonglong2 v0 = *reinterpret_cast<const ulonglong2*>(vr);
                ulonglong2 v1 = *reinterpret_cast<const ulonglong2*>(vr + 4);
#pragma unroll
                for (int r = 0; r < 4; ++r) {
                    float p = sm.sP[h][rowb + r][kk];
                    u64 p2 = pack2(p, p);
                    fma2(acc[r][0], p2, v0.x);
                    fma2(acc[r][1], p2, v0.y);
                    fma2(acc[r][2], p2, v1.x);
                    fma2(acc[r][3], p2, v1.y);
                }
            }
#pragma unroll
            for (int r = 0; r < 4; ++r) {
                float o[8]; unpack_acc(acc[r], o);
                store8(&sm.sA[rowb + r][col0], o);
            }
        }

        // dh = upd @ WO; h_E += dh  (internal barrier makes sA visible)
        {
            u64 acc[4][4] = {};
            gemm_staged(sm.sA, wo, HIDc, acc, rowb, col0, sm.sW, tid);
#pragma unroll
            for (int r = 0; r < 4; ++r) {
                int row = rowb + r;
                if (row < Kn) {
                    float o[8]; unpack_acc(acc[r], o);
#pragma unroll
                    for (int c = 0; c < 8; ++c)
                        sm.sE[row][col0 + c] += o[c];
                }
            }
        }
        __syncthreads();
        layer_norm(sm.sE, ln1g + l * HIDc, ln1b + l * HIDc, 1.0f, tid);
        __syncthreads();

        // FF: dh = relu(h_E @ ff1 + b1) @ ff2 + b2, chunked 4x128 over FF dim
        {
            u64 accD[4][4] = {};
#pragma unroll 1
            for (int ch = 0; ch < 4; ++ch) {
                u64 accT[4][4] = {};
                gemm_staged(sm.sE, f1w + (size_t)l * HIDc * FFc + ch * 128, FFc,
                            accT, rowb, col0, sm.sW, tid);
#pragma unroll
                for (int r = 0; r < 4; ++r) {
                    float o[8]; unpack_acc(accT[r], o);
#pragma unroll
                    for (int c = 0; c < 8; ++c)
                        o[c] = fmaxf(o[c] + f1b[l * FFc + ch * 128 + col0 + c], 0.0f);
                    store8(&sm.sA[rowb + r][col0], o);
                }
                gemm_staged(sm.sA, f2w + (size_t)l * FFc * HIDc + ch * 128 * HIDc,
                            HIDc, accD, rowb, col0, sm.sW, tid);
            }
#pragma unroll
            for (int r = 0; r < 4; ++r) {
                int row = rowb + r;
                if (row < Kn) {
                    float o[8]; unpack_acc(accD[r], o);
#pragma unroll
                    for (int c = 0; c < 8; ++c)
                        sm.sE[row][col0 + c] += o[c] + f2b[l * HIDc + col0 + c];
                }
            }
        }
        __syncthreads();
        layer_norm(sm.sE, ln2g + l * HIDc, ln2b + l * HIDc, xmask[bn], tid);
        __syncthreads();
    }

    // --- h_out = h_E @ Wout + b, 400 cols in 4 chunks (all threads in all
    // chunks: staged gemms contain barriers; stores masked) ---
#pragma unroll 1
    for (int ch = 0; ch < 4; ++ch) {
        int cbase = ch * 128;
        int maxc = OUTc - cbase; if (maxc > 128) maxc = 128;   // 128,128,128,16
        u64 acc[4][4] = {};
        if (maxc == 128) {
            gemm_staged(sm.sE, Wout_w + cbase, OUTc, acc, rowb, col0, sm.sW, tid);
        } else {
            gemm_staged_clamped(sm.sE, Wout_w + cbase, OUTc, maxc, acc,
                                rowb, col0, sm.sW, tid);
        }
        if (col0 < maxc) {
#pragma unroll
            for (int r = 0; r < 4; ++r) {
                int row = rowb + r;
                if (row < Kn) {
                    float o[8]; unpack_acc(acc[r], o);
#pragma unroll
                    for (int c = 0; c < 8; ++c)
                        o[c] += Wout_b[cbase + col0 + c];
                    store8(&g_hout[((size_t)bn * Kn + row) * OUTc + cbase + col0], o);
                }
            }
        }
    }
}

// ---------------------------------------------------------------------------
// Kernel 3: merge_duplicate_edges (XLA scatter-set: last write wins)
// ---------------------------------------------------------------------------
__global__ void merge_kernel(const int* __restrict__ Eidx, float* __restrict__ out)
{
    int e  = blockIdx.x;          // 0 .. B*N*K-1
    int bn = e / Kn;
    int b  = bn / Nn;
    int n  = bn % Nn;
    int j  = Eidx[e];

    const int* backRow = Eidx + (size_t)(b * Nn + j) * Kn;
    int k2 = -1;
    for (int t = Kn - 1; t >= 0; --t) {
        if (backRow[t] == n) { k2 = t; break; }
    }
    const float4* a  = reinterpret_cast<const float4*>(g_hout + (size_t)e * OUTc);
    const float4* rv = (k2 >= 0)
        ? reinterpret_cast<const float4*>(g_hout + ((size_t)(b * Nn + j) * Kn + k2) * OUTc)
        : nullptr;
    float4* o = reinterpret_cast<float4*>(out + (size_t)e * OUTc);
    int c = threadIdx.x;
    if (c < OUTc / 4) {           // 100 float4
        float4 av = a[c];
        float4 rr = rv ? rv[c] : make_float4(0.f, 0.f, 0.f, 0.f);
        o[c] = make_float4(0.5f * (av.x + rr.x), 0.5f * (av.y + rr.y),
                           0.5f * (av.z + rr.z), 0.5f * (av.w + rr.w));
    }
}

// ---------------------------------------------------------------------------
extern "C" void kernel_launch(void* const* d_in, const int* in_sizes, int n_in,
                              void* d_out, int out_size)
{
    const float* V      = (const float*)d_in[0];
    const float* E      = (const float*)d_in[1];
    const float* xmask  = (const float*)d_in[2];
    const int*   Eidx   = (const int*)  d_in[3];
    const float* Wv_w   = (const float*)d_in[4];
    const float* Wv_b   = (const float*)d_in[5];
    const float* We_w   = (const float*)d_in[6];
    const float* We_b   = (const float*)d_in[7];
    const float* WQ     = (const float*)d_in[8];
    const float* WK     = (const float*)d_in[9];
    const float* WV     = (const float*)d_in[10];
    const float* WO     = (const float*)d_in[11];
    const float* ln1g   = (const float*)d_in[12];
    const float* ln1b   = (const float*)d_in[13];
    const float* ln2g   = (const float*)d_in[14];
    const float* ln2b   = (const float*)d_in[15];
    const float* f1w    = (const float*)d_in[16];
    const float* f1b    = (const float*)d_in[17];
    const float* f2w    = (const float*)d_in[18];
    const float* f2b    = (const float*)d_in[19];
    const float* Wout_w = (const float*)d_in[20];
    const float* Wout_b = (const float*)d_in[21];
    float* out = (float*)d_out;

    const int smem = (int)sizeof(Smem);
    cudaFuncSetAttribute(pair_layers_kernel,
                         cudaFuncAttributeMaxDynamicSharedMemorySize, smem);

    hv_kernel<<<NODES, HIDc>>>(V, Wv_w, Wv_b);
    {
        dim3 g(NODES / ROWS, Lc * 4);   // 32 x 12
        proj_kernel<<<g, 128>>>(WK, WV);
    }
    pair_layers_kernel<<<NODES, 128, smem>>>(
        E, xmask, Eidx, We_w, We_b, WQ, WK, WV, WO,
        ln1g, ln1b, ln2g, ln2b, f1w, f1b, f2w, f2b, Wout_w, Wout_b);
    merge_kernel<<<NODES * Kn, 128>>>(Eidx, out);
}

// round 17
// speedup vs baseline: 1.0019x; 1.0019x over previous
#include <cuda_runtime.h>
#include <cstdint>
#include <math.h>

// Problem constants
#define Bc     2
#define Nn     512
#define NODES  (Bc * Nn)
#define Kn     30
#define HIDc   128
#define HEADSc 4
#define Dhd    32
#define FFc    512
#define Lc     3
#define OUTc   400
#define ROWS   32    // Kn padded to 32
#define HIDP   132   // padded row stride (floats)
#define KT     16    // k-steps per staged weight tile

typedef unsigned long long u64;
typedef unsigned int       u32;

// Device scratch (allocation-free rule: __device__ globals)
__device__ float g_hV  [NODES * HIDc];
__device__ float g_PK0 [Lc * NODES * HIDc];   // h_V @ WK[l, 0:128]
__device__ float g_PK1 [Lc * NODES * HIDc];   // h_V @ WK[l, 128:256]
__device__ float g_PV0 [Lc * NODES * HIDc];   // h_V @ WV[l, 0:128]
__device__ float g_PV1 [Lc * NODES * HIDc];   // h_V @ WV[l, 128:256]
__device__ float g_hout[(size_t)NODES * Kn * OUTc];

struct Smem {
    float sW [2 * KT][HIDc]; // staged weight tiles (double buffer, 16 KB)
    float sE [ROWS][HIDP];   // current h_E
    float sA [ROWS][HIDP];   // scratch: E-in / Q / upd / FF t-chunk
    float sK [ROWS][HIDP];
    float sV [ROWS][HIDP];
    float sP [HEADSc][ROWS][ROWS];  // attention probs
    float sMa[ROWS];         // mask_attend row
    int   sIdx[ROWS];        // E_idx row
};

// ---- packed fp32x2 primitives (FFMA2 path, sm_103a) ----
__device__ __forceinline__ u64 pack2(float x, float y) {
    u64 r; asm("mov.b64 %0, {%1, %2};" : "=l"(r) : "f"(x), "f"(y)); return r;
}
__device__ __forceinline__ void unpack2(u64 v, float& x, float& y) {
    asm("mov.b64 {%0, %1}, %2;" : "=f"(x), "=f"(y) : "l"(v));
}
__device__ __forceinline__ void fma2(u64& d, u64 a, u64 b) {
    asm("fma.rn.f32x2 %0, %1, %2, %0;" : "+l"(d) : "l"(a), "l"(b));
}

// ---- cp.async helpers ----
__device__ __forceinline__ void cp_async16(u32 dst, const void* src) {
    asm volatile("cp.async.cg.shared.global [%0], [%1], 16;\n" :: "r"(dst), "l"(src));
}
__device__ __forceinline__ void cp_commit() {
    asm volatile("cp.async.commit_group;\n" ::: "memory");
}
__device__ __forceinline__ void cp_wait0() {
    asm volatile("cp.async.wait_group 0;\n" ::: "memory");
}

// Stage KT k-rows x 128 cols of W into sW[buf]. 128 threads: thread = (k, 64B seg).
__device__ __forceinline__ void stage_tile(
    float (*sW)[HIDc], const float* __restrict__ W, int ldw, int kt0, int tid)
{
    int k   = tid >> 3;          // 0..15
    int seg = (tid & 7) * 16;    // float offset 0,16,...,112
    const float* src = W + (size_t)(kt0 + k) * ldw + seg;
    u32 dst = (u32)__cvta_generic_to_shared(&sW[k][seg]);
#pragma unroll
    for (int i = 0; i < 4; ++i)
        cp_async16(dst + i * 16, src + i * 4);
    cp_commit();
}

// Compute one KT-step tile from staged weights.
__device__ __forceinline__ void compute_tile(
    const float (* __restrict__ buf)[HIDc], const float (* __restrict__ A)[HIDP],
    int kb, u64 acc[4][4], int rowb, int col0)
{
#pragma unroll
    for (int k = 0; k < KT; ++k) {
        ulonglong2 w0 = *reinterpret_cast<const ulonglong2*>(&buf[k][col0]);
        ulonglong2 w1 = *reinterpret_cast<const ulonglong2*>(&buf[k][col0 + 4]);
#pragma unroll
        for (int r = 0; r < 4; ++r) {
            float av = A[rowb + r][kb + k];
            u64 s = pack2(av, av);
            fma2(acc[r][0], s, w0.x);
            fma2(acc[r][1], s, w0.y);
            fma2(acc[r][2], s, w1.x);
            fma2(acc[r][3], s, w1.y);
        }
    }
}

// SMEM-staged GEMM: acc[r][j] += sum_k A[rowb+r][k] * W[k*ldw + col0 + 2j..]
// kd=128. Weight tiles staged CTA-wide via cp.async (8x less L2 traffic).
// MUST be called by all 128 threads (contains __syncthreads).
__device__ __forceinline__ void gemm_staged(
    const float (* __restrict__ A)[HIDP], const float* __restrict__ W, int ldw,
    u64 acc[4][4], int rowb, int col0, float (*sW)[HIDc], int tid)
{
    stage_tile(sW, W, ldw, 0, tid);
#pragma unroll 1
    for (int t = 0; t < HIDc / KT; ++t) {
        cp_wait0();
        __syncthreads();                 // tile t visible CTA-wide; buf[(t+1)&1] free
        if (t + 1 < HIDc / KT)
            stage_tile(sW + ((t + 1) & 1) * KT, W, ldw, (t + 1) * KT, tid);
        compute_tile(sW + (t & 1) * KT, A, t * KT, acc, rowb, col0);
    }
    __syncthreads();                     // all reads of sW/A done before caller reuses
}

// Clamped single-buffer staged GEMM (for Wout partial chunk; scalar staging).
__device__ __forceinline__ void gemm_staged_clamped(
    const float (* __restrict__ A)[HIDP], const float* __restrict__ W, int ldw,
    int maxc, u64 acc[4][4], int rowb, int col0, float (*sW)[HIDc], int tid)
{
    int k   = tid >> 3;
    int seg = (tid & 7) * 16;
#pragma unroll 1
    for (int t = 0; t < HIDc / KT; ++t) {
#pragma unroll
        for (int i = 0; i < 16; ++i) {
            int c = seg + i;
            sW[k][c] = (c < maxc) ? W[(size_t)(t * KT + k) * ldw + c] : 0.0f;
        }
        __syncthreads();
        compute_tile(sW, A, t * KT, acc, rowb, col0);
        __syncthreads();
    }
}

__device__ __forceinline__ void unpack_acc(const u64 a[4], float o[8]) {
    unpack2(a[0], o[0], o[1]); unpack2(a[1], o[2], o[3]);
    unpack2(a[2], o[4], o[5]); unpack2(a[3], o[6], o[7]);
}

__device__ __forceinline__ void store8(float* dst, const float o[8]) {
    *reinterpret_cast<float4*>(dst)     = make_float4(o[0], o[1], o[2], o[3]);
    *reinterpret_cast<float4*>(dst + 4) = make_float4(o[4], o[5], o[6], o[7]);
}

// Register-pipelined LDG GEMM (kept for the small proj kernel).
__device__ __forceinline__ void gemm_acc2(
    const float (* __restrict__ A)[HIDP], const float* __restrict__ W, int ldw,
    u64 acc[4][4], int rowb, int col0)
{
    const float* wp = W + col0;
    ulonglong2 a0[4], a1[4], b0[4], b1[4];
#pragma unroll
    for (int k = 0; k < 4; ++k) {
        const float* p = wp + (size_t)k * ldw;
        a0[k] = *reinterpret_cast<const ulonglong2*>(p);
        a1[k] = *reinterpret_cast<const ulonglong2*>(p + 4);
    }
#pragma unroll 1
    for (int kb = 0; kb < HIDc; kb += 8) {
#pragma unroll
        for (int k = 0; k < 4; ++k) {
            const float* p = wp + (size_t)(kb + 4 + k) * ldw;
            b0[k] = *reinterpret_cast<const ulonglong2*>(p);
            b1[k] = *reinterpret_cast<const ulonglong2*>(p + 4);
        }
#pragma unroll
        for (int k = 0; k < 4; ++k)
#pragma unroll
            for (int r = 0; r < 4; ++r) {
                float av = A[rowb + r][kb + k];
                u64 s = pack2(av, av);
                fma2(acc[r][0], s, a0[k].x); fma2(acc[r][1], s, a0[k].y);
                fma2(acc[r][2], s, a1[k].x); fma2(acc[r][3], s, a1[k].y);
            }
        if (kb + 8 < HIDc) {
#pragma unroll
            for (int k = 0; k < 4; ++k) {
                const float* p = wp + (size_t)(kb + 8 + k) * ldw;
                a0[k] = *reinterpret_cast<const ulonglong2*>(p);
                a1[k] = *reinterpret_cast<const ulonglong2*>(p + 4);
            }
        }
#pragma unroll
        for (int k = 0; k < 4; ++k)
#pragma unroll
            for (int r = 0; r < 4; ++r) {
                float av = A[rowb + r][kb + 4 + k];
                u64 s = pack2(av, av);
                fma2(acc[r][0], s, b0[k].x); fma2(acc[r][1], s, b0[k].y);
                fma2(acc[r][2], s, b1[k].x); fma2(acc[r][3], s, b1[k].y);
            }
    }
}

// Reference norm: mu=mean, sigma=sqrt(var_ddof1+1e-6),
// out = (g*(x-mu)/(sigma+1e-6)+b)*scale
__device__ __forceinline__ void layer_norm(
    float (*X)[HIDP], const float* __restrict__ g, const float* __restrict__ bta,
    float scale, int tid)
{
    int lane = tid & 31, wid = tid >> 5;
    for (int row = wid; row < Kn; row += 4) {
        float v0 = X[row][lane], v1 = X[row][lane + 32];
        float v2 = X[row][lane + 64], v3 = X[row][lane + 96];
        float s = v0 + v1 + v2 + v3;
#pragma unroll
        for (int o = 16; o; o >>= 1) s += __shfl_xor_sync(0xffffffffu, s, o);
        float mu = s * (1.0f / HIDc);
        float d0 = v0 - mu, d1 = v1 - mu, d2 = v2 - mu, d3 = v3 - mu;
        float vs = d0 * d0 + d1 * d1 + d2 * d2 + d3 * d3;
#pragma unroll
        for (int o = 16; o; o >>= 1) vs += __shfl_xor_sync(0xffffffffu, vs, o);
        float sigma = sqrtf(vs * (1.0f / (HIDc - 1)) + 1e-6f);
        float invs = 1.0f / (sigma + 1e-6f);
        X[row][lane]      = (g[lane]      * d0 * invs + bta[lane])      * scale;
        X[row][lane + 32] = (g[lane + 32] * d1 * invs + bta[lane + 32]) * scale;
        X[row][lane + 64] = (g[lane + 64] * d2 * invs + bta[lane + 64]) * scale;
        X[row][lane + 96] = (g[lane + 96] * d3 * invs + bta[lane + 96]) * scale;
    }
}

// ---------------------------------------------------------------------------
// Kernel 1: h_V = V @ Wv_w + Wv_b
// ---------------------------------------------------------------------------
__global__ void hv_kernel(const float* __restrict__ V,
                          const float* __restrict__ Wv_w,
                          const float* __restrict__ Wv_b)
{
    __shared__ float sv[HIDc];
    int bn = blockIdx.x;
    int tid = threadIdx.x;
    sv[tid] = V[(size_t)bn * HIDc + tid];
    __syncthreads();
    float acc = Wv_b[tid];
#pragma unroll 8
    for (int k = 0; k < HIDc; ++k)
        acc = fmaf(sv[k], Wv_w[k * HIDc + tid], acc);
    g_hV[(size_t)bn * HIDc + tid] = acc;
}

// ---------------------------------------------------------------------------
// Kernel 1b: per-node projections. blockIdx.x = node tile (32 nodes),
// blockIdx.y = l*4 + t,  t in {PK0, PK1, PV0, PV1}.
// ---------------------------------------------------------------------------
__global__ void __launch_bounds__(128)
proj_kernel(const float* __restrict__ WK, const float* __restrict__ WV)
{
    __shared__ float sHV[ROWS][HIDP];
    const int tid  = threadIdx.x;
    const int node0 = blockIdx.x * ROWS;
    const int j    = blockIdx.y;
    const int l    = j >> 2;
    const int t    = j & 3;
    const int rowb = (tid >> 4) * 4;
    const int col0 = (tid & 15) * 8;

    for (int i = tid; i < ROWS * HIDc; i += 128) {
        int r = i >> 7, c = i & 127;
        sHV[r][c] = g_hV[(size_t)(node0 + r) * HIDc + c];
    }
    __syncthreads();

    const float* W = ((t < 2) ? WK : WV) + (size_t)l * 3 * HIDc * HIDc
                     + (size_t)(t & 1) * HIDc * HIDc;
    float* out = (t == 0 ? g_PK0 : t == 1 ? g_PK1 : t == 2 ? g_PV0 : g_PV1)
                 + (size_t)l * NODES * HIDc;

    u64 acc[4][4] = {};
    gemm_acc2(sHV, W, HIDc, acc, rowb, col0);
#pragma unroll
    for (int r = 0; r < 4; ++r) {
        float o[8]; unpack_acc(acc[r], o);
        store8(&out[(size_t)(node0 + rowb + r) * HIDc + col0], o);
    }
}

// ---------------------------------------------------------------------------
// Kernel 2: fused h_E init + 3 transformer layers + output projection.
// One block per (b,n). 128 threads, 2 blocks/SM. Weights staged in SMEM.
// ---------------------------------------------------------------------------
extern "C" __global__ void __launch_bounds__(128, 2)
pair_layers_kernel(
    const float* __restrict__ E, const float* __restrict__ xmask,
    const int* __restrict__ Eidx,
    const float* __restrict__ We_w, const float* __restrict__ We_b,
    const float* __restrict__ WQ, const float* __restrict__ WK,
    const float* __restrict__ WV, const float* __restrict__ WO,
    const float* __restrict__ ln1g, const float* __restrict__ ln1b,
    const float* __restrict__ ln2g, const float* __restrict__ ln2b,
    const float* __restrict__ f1w, const float* __restrict__ f1b,
    const float* __restrict__ f2w, const float* __restrict__ f2b,
    const float* __restrict__ Wout_w, const float* __restrict__ Wout_b)
{
    extern __shared__ char smraw[];
    Smem& sm = *reinterpret_cast<Smem*>(smraw);

    const int bn   = blockIdx.x;
    const int b    = bn / Nn;
    const int tid  = threadIdx.x;
    const int rowb = (tid >> 4) * 4;        // 4 rows per thread
    const int col0 = (tid & 15) * 8;        // 8 cols per thread

    // --- Stage inputs ---
    const int* eRow = Eidx + (size_t)bn * Kn;
    const float* Eblk = E + (size_t)bn * Kn * HIDc;
    for (int i = tid; i < ROWS * HIDc; i += 128) {
        int r = i >> 7, c = i & 127;
        sm.sA[r][c] = (r < Kn) ? Eblk[r * HIDc + c] : 0.0f;
    }
    if (tid < ROWS) {
        int j = (tid < Kn) ? eRow[tid] : 0;
        sm.sIdx[tid] = j;
        sm.sMa[tid] = (tid < Kn) ? xmask[b * Nn + j] * xmask[bn] : 0.0f;
    }
    __syncthreads();

    // --- h_E = E @ We_w + We_b ---
    {
        u64 acc[4][4] = {};
        gemm_staged(sm.sA, We_w, HIDc, acc, rowb, col0, sm.sW, tid);
#pragma unroll
        for (int r = 0; r < 4; ++r) {
            int row = rowb + r;
            float o[8]; unpack_acc(acc[r], o);
#pragma unroll
            for (int c = 0; c < 8; ++c)
                o[c] = (row < Kn) ? o[c] + We_b[col0 + c] : 0.0f;
            store8(&sm.sE[row][col0], o);
        }
    }
    // sE stores become visible via the first internal barrier of the next gemm.

    const float att_scale = 0.17677669529663689f;  // 1/sqrt(32)

#pragma unroll 1
    for (int l = 0; l < Lc; ++l) {
        const float* wq  = WQ + (size_t)l * HIDc * HIDc;
        const float* wk2 = WK + (size_t)l * 3 * HIDc * HIDc + 2 * HIDc * HIDc;
        const float* wv2 = WV + (size_t)l * 3 * HIDc * HIDc + 2 * HIDc * HIDc;
        const float* wo  = WO + (size_t)l * HIDc * HIDc;

        // Gather per-node precomputed K/V contributions into sK/sV.
        {
            int self = sm.sIdx[0];
            const float* pk0 = g_PK0 + ((size_t)l * NODES + b * Nn + self) * HIDc;
            const float* pv0 = g_PV0 + ((size_t)l * NODES + b * Nn + self) * HIDc;
            float k0 = pk0[tid], v0 = pv0[tid];
#pragma unroll 2
            for (int r = 0; r < Kn; ++r) {
                size_t nidx = (size_t)l * NODES + b * Nn + sm.sIdx[r];
                sm.sK[r][tid] = k0 + g_PK1[nidx * HIDc + tid];
                sm.sV[r][tid] = v0 + g_PV1[nidx * HIDc + tid];
            }
            sm.sK[30][tid] = 0.0f; sm.sK[31][tid] = 0.0f;
            sm.sV[30][tid] = 0.0f; sm.sV[31][tid] = 0.0f;
        }

        // Q = h_E @ WQ  (internal barriers make sE + gathered sK/sV visible)
        {
            u64 qacc[4][4] = {};
            gemm_staged(sm.sE, wq, HIDc, qacc, rowb, col0, sm.sW, tid);
#pragma unroll
            for (int r = 0; r < 4; ++r) {
                float o[8]; unpack_acc(qacc[r], o);
                store8(&sm.sA[rowb + r][col0], o);
            }
        }

        // K += h_E @ WK2 ; V += h_E @ WV2  (seed from gathered tiles; regions
        // read/written per-thread disjoint)
        {
            u64 acc[4][4];
#pragma unroll
            for (int r = 0; r < 4; ++r)
#pragma unroll
                for (int jj = 0; jj < 4; ++jj)
                    acc[r][jj] = *reinterpret_cast<const u64*>(&sm.sK[rowb + r][col0 + 2 * jj]);
            gemm_staged(sm.sE, wk2, HIDc, acc, rowb, col0, sm.sW, tid);
#pragma unroll
            for (int r = 0; r < 4; ++r) {
                float o[8]; unpack_acc(acc[r], o);
                store8(&sm.sK[rowb + r][col0], o);
            }
        }
        {
            u64 acc[4][4];
#pragma unroll
            for (int r = 0; r < 4; ++r)
#pragma unroll
                for (int jj = 0; jj < 4; ++jj)
                    acc[r][jj] = *reinterpret_cast<const u64*>(&sm.sV[rowb + r][col0 + 2 * jj]);
            gemm_staged(sm.sE, wv2, HIDc, acc, rowb, col0, sm.sW, tid);
#pragma unroll
            for (int r = 0; r < 4; ++r) {
                float o[8]; unpack_acc(acc[r], o);
                store8(&sm.sV[rowb + r][col0], o);
            }
        }
        __syncthreads();   // Q (sA), K, V stores visible CTA-wide for logits

        // logits (masked) -> sP
        for (int idx = tid; idx < HEADSc * Kn * Kn; idx += 128) {
            int h   = idx / (Kn * Kn);
            int rem = idx % (Kn * Kn);
            int q   = rem / Kn;
            int kk  = rem % Kn;
            const u64* qp = reinterpret_cast<const u64*>(&sm.sA[q][h * Dhd]);
            const u64* kp = reinterpret_cast<const u64*>(&sm.sK[kk][h * Dhd]);
            u64 acc = 0ULL;
#pragma unroll
            for (int d = 0; d < Dhd / 2; ++d) fma2(acc, qp[d], kp[d]);
            float lo, hi; unpack2(acc, lo, hi);
            float dot = lo + hi;
            float m = sm.sMa[q] * sm.sMa[kk];
            sm.sP[h][q][kk] = (m > 0.0f) ? dot * att_scale : -3.402823466e38f;
        }
        __syncthreads();

        // softmax over kk, then * mask
        if (tid < HEADSc * Kn) {
            int h = tid / Kn, q = tid % Kn;
            float mx = -3.402823466e38f;
            for (int kk = 0; kk < Kn; ++kk) mx = fmaxf(mx, sm.sP[h][q][kk]);
            float s = 0.0f;
            for (int kk = 0; kk < Kn; ++kk) {
                float e = __expf(sm.sP[h][q][kk] - mx);
                sm.sP[h][q][kk] = e;
                s += e;
            }
            float inv = 1.0f / s;
            float mq = sm.sMa[q];
            for (int kk = 0; kk < Kn; ++kk)
                sm.sP[h][q][kk] = sm.sP[h][q][kk] * inv * (mq * sm.sMa[kk]);
        }
        __syncthreads();

        // upd = P @ V (per head) -> sA (Q dead; logits barrier passed)
        {
            u64 acc[4][4] = {};
            int h = col0 >> 5;
            for (int kk = 0; kk < Kn; ++kk) {
                const float* vr = &sm.sV[kk][col0];
                ulonglong2 v0 = *reinterpret_cast<const ulonglong2*>(vr);
                ulonglong2 v1 = *reinterpret_cast<const ulonglong2*>(vr + 4);
#pragma unroll
                for (int r = 0; r < 4; ++r) {
                    float p = sm.sP[h][rowb + r][kk];
                    u64 p2 = pack2(p, p);
                    fma2(acc[r][0], p2, v0.x);
                    fma2(acc[r][1], p2, v0.y);
                    fma2(acc[r][2], p2, v1.x);
                    fma2(acc[r][3], p2, v1.y);
                }
            }
#pragma unroll
            for (int r = 0; r < 4; ++r) {
                float o[8]; unpack_acc(acc[r], o);
                store8(&sm.sA[rowb + r][col0], o);
            }
        }

        // dh = upd @ WO; h_E += dh  (internal barrier makes sA visible)
        {
            u64 acc[4][4] = {};
            gemm_staged(sm.sA, wo, HIDc, acc, rowb, col0, sm.sW, tid);
#pragma unroll
            for (int r = 0; r < 4; ++r) {
                int row = rowb + r;
                if (row < Kn) {
                    float o[8]; unpack_acc(acc[r], o);
#pragma unroll
                    for (int c = 0; c < 8; ++c)
                        sm.sE[row][col0 + c] += o[c];
                }
            }
        }
        __syncthreads();
        layer_norm(sm.sE, ln1g + l * HIDc, ln1b + l * HIDc, 1.0f, tid);
        __syncthreads();

        // FF: dh = relu(h_E @ ff1 + b1) @ ff2 + b2, chunked 4x128 over FF dim
        {
            u64 accD[4][4] = {};
#pragma unroll 1
            for (int ch = 0; ch < 4; ++ch) {
                u64 accT[4][4] = {};
                gemm_staged(sm.sE, f1w + (size_t)l * HIDc * FFc + ch * 128, FFc,
                            accT, rowb, col0, sm.sW, tid);
#pragma unroll
                for (int r = 0; r < 4; ++r) {
                    float o[8]; unpack_acc(accT[r], o);
#pragma unroll
                    for (int c = 0; c < 8; ++c)
                        o[c] = fmaxf(o[c] + f1b[l * FFc + ch * 128 + col0 + c], 0.0f);
                    store8(&sm.sA[rowb + r][col0], o);
                }
                gemm_staged(sm.sA, f2w + (size_t)l * FFc * HIDc + ch * 128 * HIDc,
                            HIDc, accD, rowb, col0, sm.sW, tid);
            }
#pragma unroll
            for (int r = 0; r < 4; ++r) {
                int row = rowb + r;
                if (row < Kn) {
                    float o[8]; unpack_acc(accD[r], o);
#pragma unroll
                    for (int c = 0; c < 8; ++c)
                        sm.sE[row][col0 + c] += o[c] + f2b[l * HIDc + col0 + c];
                }
            }
        }
        __syncthreads();
        layer_norm(sm.sE, ln2g + l * HIDc, ln2b + l * HIDc, xmask[bn], tid);
        __syncthreads();
    }

    // --- h_out = h_E @ Wout + b, 400 cols in 4 chunks (all threads in all
    // chunks: staged gemms contain barriers; stores masked) ---
#pragma unroll 1
    for (int ch = 0; ch < 4; ++ch) {
        int cbase = ch * 128;
        int maxc = OUTc - cbase; if (maxc > 128) maxc = 128;   // 128,128,128,16
        u64 acc[4][4] = {};
        if (maxc == 128) {
            gemm_staged(sm.sE, Wout_w + cbase, OUTc, acc, rowb, col0, sm.sW, tid);
        } else {
            gemm_staged_clamped(sm.sE, Wout_w + cbase, OUTc, maxc, acc,
                                rowb, col0, sm.sW, tid);
        }
        if (col0 < maxc) {
#pragma unroll
            for (int r = 0; r < 4; ++r) {
                int row = rowb + r;
                if (row < Kn) {
                    float o[8]; unpack_acc(acc[r], o);
#pragma unroll
                    for (int c = 0; c < 8; ++c)
                        o[c] += Wout_b[cbase + col0 + c];
                    store8(&g_hout[((size_t)bn * Kn + row) * OUTc + cbase + col0], o);
                }
            }
        }
    }
}

// ---------------------------------------------------------------------------
// Kernel 3: merge_duplicate_edges (XLA scatter-set: last write wins)
// ---------------------------------------------------------------------------
__global__ void merge_kernel(const int* __restrict__ Eidx, float* __restrict__ out)
{
    int e  = blockIdx.x;          // 0 .. B*N*K-1
    int bn = e / Kn;
    int b  = bn / Nn;
    int n  = bn % Nn;
    int j  = Eidx[e];

    const int* backRow = Eidx + (size_t)(b * Nn + j) * Kn;
    int k2 = -1;
    for (int t = Kn - 1; t >= 0; --t) {
        if (backRow[t] == n) { k2 = t; break; }
    }
    const float4* a  = reinterpret_cast<const float4*>(g_hout + (size_t)e * OUTc);
    const float4* rv = (k2 >= 0)
        ? reinterpret_cast<const float4*>(g_hout + ((size_t)(b * Nn + j) * Kn + k2) * OUTc)
        : nullptr;
    float4* o = reinterpret_cast<float4*>(out + (size_t)e * OUTc);
    int c = threadIdx.x;
    if (c < OUTc / 4) {           // 100 float4
        float4 av = a[c];
        float4 rr = rv ? rv[c] : make_float4(0.f, 0.f, 0.f, 0.f);
        o[c] = make_float4(0.5f * (av.x + rr.x), 0.5f * (av.y + rr.y),
                           0.5f * (av.z + rr.z), 0.5f * (av.w + rr.w));
    }
}

// ---------------------------------------------------------------------------
extern "C" void kernel_launch(void* const* d_in, const int* in_sizes, int n_in,
                              void* d_out, int out_size)
{
    const float* V      = (const float*)d_in[0];
    const float* E      = (const float*)d_in[1];
    const float* xmask  = (const float*)d_in[2];
    const int*   Eidx   = (const int*)  d_in[3];
    const float* Wv_w   = (const float*)d_in[4];
    const float* Wv_b   = (const float*)d_in[5];
    const float* We_w   = (const float*)d_in[6];
    const float* We_b   = (const float*)d_in[7];
    const float* WQ     = (const float*)d_in[8];
    const float* WK     = (const float*)d_in[9];
    const float* WV     = (const float*)d_in[10];
    const float* WO     = (const float*)d_in[11];
    const float* ln1g   = (const float*)d_in[12];
    const float* ln1b   = (const float*)d_in[13];
    const float* ln2g   = (const float*)d_in[14];
    const float* ln2b   = (const float*)d_in[15];
    const float* f1w    = (const float*)d_in[16];
    const float* f1b    = (const float*)d_in[17];
    const float* f2w    = (const float*)d_in[18];
    const float* f2b    = (const float*)d_in[19];
    const float* Wout_w = (const float*)d_in[20];
    const float* Wout_b = (const float*)d_in[21];
    float* out = (float*)d_out;

    const int smem = (int)sizeof(Smem);
    cudaFuncSetAttribute(pair_layers_kernel,
                         cudaFuncAttributeMaxDynamicSharedMemorySize, smem);

    hv_kernel<<<NODES, HIDc>>>(V, Wv_w, Wv_b);
    {
        dim3 g(NODES / ROWS, Lc * 4);   // 32 x 12
        proj_kernel<<<g, 128>>>(WK, WV);
    }
    pair_layers_kernel<<<NODES, 128, smem>>>(
        E, xmask, Eidx, We_w, We_b, WQ, WK, WV, WO,
        ln1g, ln1b, ln2g, ln2b, f1w, f1b, f2w, f2b, Wout_w, Wout_b);
    merge_kernel<<<NODES * Kn, 128>>>(Eidx, out);
}